// round 14
// baseline (speedup 1.0000x reference)
#include <cuda_runtime.h>
#include <math.h>

// Problem: input (8, 64, 64, 3) fp32 -> scalar fp32.
#define NB   8
#define NPIX 4096            // 64*64
#define NELE (NB * NPIX)     // 32768
#define PRE_BLKS 64
#define MAIN_BLKS 288        // triangular block set (see c_off)

// ---- scratch (no allocations allowed -> __device__ globals) ----
__device__ __align__(16) float g_a[NELE];        // |x|.sum(-1), layout [b][i]
__device__ __align__(16) float g_t[NELE];        // same values, pixel-major [i][b]
__device__ __align__(16) float g_dtab[64 * 128]; // sqrt(dy^2+dx^2), [dy][dx+63]
__device__ unsigned int g_minbits = 0x7F800000u; // +inf (a >= 0 -> uint order ok)
__device__ unsigned int g_maxbits = 0u;
__device__ double       g_part[MAIN_BLKS];
__device__ unsigned int g_cnt_main = 0;          // self-resetting counter

// i-tile = 8 rows (bx 0..7). For each bx, jy in [8bx, 64) -> 64-8bx blocks.
__constant__ int c_off[9] = {0, 64, 120, 168, 208, 240, 264, 280, 288};

// ---- packed f32x2 helpers (Blackwell FFMA2 — only reachable via PTX) ----
__device__ __forceinline__ unsigned long long pk2(float lo, float hi) {
    unsigned long long r;
    asm("mov.b64 %0, {%1,%2};" : "=l"(r) : "f"(lo), "f"(hi));
    return r;
}
__device__ __forceinline__ void unpk2(unsigned long long v, float& lo, float& hi) {
    asm("mov.b64 {%0,%1}, %2;" : "=f"(lo), "=f"(hi) : "l"(v));
}
__device__ __forceinline__ unsigned long long mul2(unsigned long long a, unsigned long long b) {
    unsigned long long r;
    asm("mul.rn.f32x2 %0, %1, %2;" : "=l"(r) : "l"(a), "l"(b));
    return r;
}
__device__ __forceinline__ unsigned long long fma2(unsigned long long a, unsigned long long b,
                                                   unsigned long long c) {
    unsigned long long r;
    asm("fma.rn.f32x2 %0, %1, %2, %3;" : "=l"(r) : "l"(a), "l"(b), "l"(c));
    return r;
}

// ---------------------------------------------------------------
// 4 pixels/thread (3 x LDG.128). Writes g_a (batch-major), g_t (pixel-major),
// the 64x128 distance table (one entry/thread), and global min/max via
// uint-bit atomics (single phase; k_main derives inv/nb after the PDL wait).
__global__ void __launch_bounds__(128) k_pre(const float4* __restrict__ in4) {
    int t = blockIdx.x * 128 + threadIdx.x;            // 0..8191
    float4 a = in4[t * 3 + 0];
    float4 b = in4[t * 3 + 1];
    float4 c = in4[t * 3 + 2];

    // distance table entry: t = dy*128 + m, dx = m - 63
    {
        int dy = t >> 7, dx = (t & 127) - 63;
        g_dtab[t] = sqrtf((float)(dy * dy + dx * dx));
    }

    float4 s;
    s.x = fabsf(a.x) + fabsf(a.y) + fabsf(a.z);
    s.y = fabsf(a.w) + fabsf(b.x) + fabsf(b.y);
    s.z = fabsf(b.z) + fabsf(b.w) + fabsf(c.x);
    s.w = fabsf(c.y) + fabsf(c.z) + fabsf(c.w);
    *(float4*)&g_a[t * 4] = s;

    int bb = t >> 10;                                  // batch
    int p0 = (t & 1023) * 4;                           // first pixel
    g_t[(p0 + 0) * 8 + bb] = s.x;
    g_t[(p0 + 1) * 8 + bb] = s.y;
    g_t[(p0 + 2) * 8 + bb] = s.z;
    g_t[(p0 + 3) * 8 + bb] = s.w;

    float mn = fminf(fminf(s.x, s.y), fminf(s.z, s.w));
    float mx = fmaxf(fmaxf(s.x, s.y), fmaxf(s.z, s.w));
    #pragma unroll
    for (int o = 16; o; o >>= 1) {
        mn = fminf(mn, __shfl_xor_sync(0xffffffffu, mn, o));
        mx = fmaxf(mx, __shfl_xor_sync(0xffffffffu, mx, o));
    }
    __shared__ float smn[4], smx[4];
    int wid = threadIdx.x >> 5, lid = threadIdx.x & 31;
    if (lid == 0) { smn[wid] = mn; smx[wid] = mx; }
    __syncthreads();
    if (threadIdx.x == 0) {
        #pragma unroll
        for (int w = 1; w < 4; w++) { mn = fminf(mn, smn[w]); mx = fmaxf(mx, smx[w]); }
        atomicMin(&g_minbits, __float_as_uint(mn));
        atomicMax(&g_maxbits, __float_as_uint(mx));
    }
}

// ---------------------------------------------------------------
// Symmetric main kernel, 4-pixel register tile. 288 blocks x 128 threads.
// Block = (i-tile of 8 rows = 512 px) x (full j-row of 64); only jy >= ry0
// launched, pair weight {0,1,2} folded into the per-block distance tile
// (gathered from g_dtab in L2 — no MUFU in this kernel).
// Thread: ix = tid&63, rg = tid>>6; owns pixel rows ry0+rg+{0,2,4,6}.
// Inner loop per jj: 3 x LDS.128 + 20 FFMA2 covering 32 pair-MACs.
__global__ void __launch_bounds__(128) k_main(float* __restrict__ out) {
    __shared__ __align__(16) float4 s_dd[256];         // [rg 0..1][m 0..127]: d for 4 rows
    __shared__ __align__(16) float  s_fj[512];         // 64 j x 8 b, pixel-major
    __shared__ double s_red[4];
    __shared__ bool   s_last;

    int tid  = threadIdx.x;
    int lane = tid & 31, wid = tid >> 5;
    int ix   = tid & 63, rg = tid >> 6;                // 0 or 1

    // ---- decode (bx, jy) ----
    int bid = blockIdx.x;
    int bx = 0;
    #pragma unroll
    for (int t = 1; t < 8; t++) bx += (bid >= c_off[t]);
    int jy  = (bid - c_off[bx]) + 8 * bx;
    int ry0 = bx * 8;

    // ---- wait for k_pre (PDL; all its global writes are then visible) ----
    asm volatile("griddepcontrol.wait;" ::: "memory");

    float mn  = __uint_as_float(g_minbits);
    float mx  = __uint_as_float(g_maxbits);
    float inv = 1.0f / (mx - mn);
    float nb  = -mn * inv;                              // f = fma(a, inv, nb)

    // ---- weighted distance tile from g_dtab: 2 float4 entries/thread ----
    #pragma unroll
    for (int e = tid; e < 256; e += 128) {
        int erg = e >> 7, m = e & 127;
        float v[4];
        #pragma unroll
        for (int k = 0; k < 4; k++) {
            int dy  = jy - (ry0 + erg + 2 * k);
            int ady = dy < 0 ? -dy : dy;
            float w = (dy > 0) ? 2.0f : (dy == 0 ? 1.0f : 0.0f);
            v[k] = w * g_dtab[ady * 128 + m];
        }
        s_dd[e] = make_float4(v[0], v[1], v[2], v[3]);
    }

    // ---- normalized f of the full j row (coalesced from batch-major) ----
    #pragma unroll
    for (int e = tid; e < 512; e += 128) {
        int b = e >> 6, x = e & 63;
        s_fj[x * 8 + b] = fmaf(g_a[b * NPIX + jy * 64 + x], inv, nb);
    }

    // ---- this thread's four pixels from the pixel-major mirror ----
    unsigned long long f[4][4];
    #pragma unroll
    for (int p = 0; p < 4; p++) {
        int ip = bx * 512 + (rg + 2 * p) * 64 + ix;
        float4 lo = *(const float4*)&g_t[ip * 8];
        float4 hi = *(const float4*)&g_t[ip * 8 + 4];
        f[p][0] = pk2(fmaf(lo.x, inv, nb), fmaf(lo.y, inv, nb));
        f[p][1] = pk2(fmaf(lo.z, inv, nb), fmaf(lo.w, inv, nb));
        f[p][2] = pk2(fmaf(hi.x, inv, nb), fmaf(hi.y, inv, nb));
        f[p][3] = pk2(fmaf(hi.z, inv, nb), fmaf(hi.w, inv, nb));
    }
    __syncthreads();

    // signed index m = ix - jj + 63
    const float4* dbase = s_dd + (rg << 7) + (ix + 63);

    unsigned long long acc[4] = {0ull, 0ull, 0ull, 0ull};  // 4 independent chains
    #pragma unroll 16
    for (int jj = 0; jj < 64; jj++) {
        ulonglong2 ja = *(const ulonglong2*)(s_fj + jj * 8);      // b 0..3
        ulonglong2 jb = *(const ulonglong2*)(s_fj + jj * 8 + 4);  // b 4..7
        float4 d4 = dbase[-jj];                         // d for rows rg+{0,2,4,6}

        {
            unsigned long long t0 = mul2(f[0][0], ja.x);
            t0 = fma2(f[0][1], ja.y, t0);
            t0 = fma2(f[0][2], jb.x, t0);
            t0 = fma2(f[0][3], jb.y, t0);
            acc[0] = fma2(t0, pk2(d4.x, d4.x), acc[0]);
        }
        {
            unsigned long long t1 = mul2(f[1][0], ja.x);
            t1 = fma2(f[1][1], ja.y, t1);
            t1 = fma2(f[1][2], jb.x, t1);
            t1 = fma2(f[1][3], jb.y, t1);
            acc[1] = fma2(t1, pk2(d4.y, d4.y), acc[1]);
        }
        {
            unsigned long long t2 = mul2(f[2][0], ja.x);
            t2 = fma2(f[2][1], ja.y, t2);
            t2 = fma2(f[2][2], jb.x, t2);
            t2 = fma2(f[2][3], jb.y, t2);
            acc[2] = fma2(t2, pk2(d4.z, d4.z), acc[2]);
        }
        {
            unsigned long long t3 = mul2(f[3][0], ja.x);
            t3 = fma2(f[3][1], ja.y, t3);
            t3 = fma2(f[3][2], jb.x, t3);
            t3 = fma2(f[3][3], jb.y, t3);
            acc[3] = fma2(t3, pk2(d4.w, d4.w), acc[3]);
        }
    }

    double dacc = 0.0;
    #pragma unroll
    for (int p = 0; p < 4; p++) {
        float lo, hi;
        unpk2(acc[p], lo, hi);
        dacc += (double)lo + (double)hi;
    }
    #pragma unroll
    for (int o = 16; o; o >>= 1)
        dacc += __shfl_xor_sync(0xffffffffu, dacc, o);
    if (lane == 0) s_red[wid] = dacc;
    __syncthreads();
    if (tid == 0) {
        double s = s_red[0] + s_red[1] + s_red[2] + s_red[3];
        g_part[bid] = s;
        __threadfence();
        s_last = (atomicAdd(&g_cnt_main, 1u) == (MAIN_BLKS - 1u));
    }
    __syncthreads();

    // ---- last block reduces all partials (fixed order -> deterministic) ----
    if (s_last) {
        double s = ((volatile double*)g_part)[tid]
                 + ((volatile double*)g_part)[tid + 128];
        if (tid < 32) s += ((volatile double*)g_part)[tid + 256];
        #pragma unroll
        for (int o = 16; o; o >>= 1)
            s += __shfl_xor_sync(0xffffffffu, s, o);
        if (lane == 0) s_red[wid] = s;
        __syncthreads();
        if (tid == 0) {
            double t = s_red[0] + s_red[1] + s_red[2] + s_red[3];
            out[0] = (float)(t / 134217728.0);          // / (B*N*N)
            g_cnt_main = 0;                             // reset for graph replay
            g_minbits  = 0x7F800000u;
            g_maxbits  = 0u;
        }
    }
}

extern "C" void kernel_launch(void* const* d_in, const int* in_sizes, int n_in,
                              void* d_out, int out_size) {
    const float4* in4 = (const float4*)d_in[0];
    float*        out = (float*)d_out;

    k_pre<<<PRE_BLKS, 128>>>(in4);

    // k_main with programmatic dependent launch: prologue overlaps k_pre;
    // griddepcontrol.wait gates the data-dependent part.
    cudaLaunchConfig_t cfg = {};
    cfg.gridDim  = dim3(MAIN_BLKS);
    cfg.blockDim = dim3(128);
    cudaLaunchAttribute attr[1];
    attr[0].id = cudaLaunchAttributeProgrammaticStreamSerialization;
    attr[0].val.programmaticStreamSerializationAllowed = 1;
    cfg.attrs    = attr;
    cfg.numAttrs = 1;
    cudaLaunchKernelEx(&cfg, k_main, out);
}